// round 12
// baseline (speedup 1.0000x reference)
#include <cuda_runtime.h>
#include <math.h>

#define S   512
#define B   64
#define H   256
#define NH  4
#define NHH 1024      // NH*H
#define NCTA 128
#define JC  16        // j-columns per CTA
#define BC  8         // batches per CTA
#define WROW 260      // padded row stride (floats) for conflict-free LDS

// ---------------- device globals (no runtime allocation allowed) ------------
__device__ float g_P[(size_t)S * H * B];       // [t][j][b]  : x@Wi.T
__device__ float g_gate[(size_t)S * B * NH];   // [t][b][nh] : sigmoid gates
// cand, ping-pong, packed {tag(hi32)=t, value(lo32)} per (j,b). Single 8B
// store/load is atomic -> tag rides with data, no fences needed.
__device__ unsigned long long g_cand[2][H * B];
__device__ float g_sel[B * NHH];               // hcat at t = len-1

// ---------------- init: reset cand tags to sentinel each replay -------------
__global__ void init_kernel() {
    int i = blockIdx.x * blockDim.x + threadIdx.x;      // 0 .. 16383
    const unsigned long long sent = 0xFFFFFFFF00000000ULL;
    g_cand[0][i] = sent;
    g_cand[1][i] = sent;
}

// ---------------- gate precompute: g = sigmoid(d - 3*nh) --------------------
__global__ __launch_bounds__(256)
void gate_kernel(const float* __restrict__ fix_src) {
    int t = blockIdx.x;
    int tid = threadIdx.x;          // b = tid>>2, nh = tid&3
    int b = tid >> 2, nh = tid & 3;
    float d = fix_src[b * S + t];
    g_gate[(size_t)t * (B * NH) + tid] = 1.0f / (1.0f + expf(3.0f * (float)nh - d));
}

// ---------------- P precompute: P[t][j][b] = emb[src[b,t]] . Wi[j,:] --------
__global__ __launch_bounds__(256, 2)
void p_kernel(const int* __restrict__ src, const float* __restrict__ emb,
              const float* __restrict__ Wi) {
    __shared__ float s_x[32][256];
    __shared__ int s_tok[32];
    const int t = blockIdx.x >> 1, bh = blockIdx.x & 1;
    const int tid = threadIdx.x;

    if (tid < 32) s_tok[tid] = src[(bh * 32 + tid) * S + t];
    __syncthreads();
    {
        int row = tid >> 3, seg = tid & 7;
        const float4* sp = (const float4*)(emb + (size_t)s_tok[row] * H) + seg * 8;
        float4* dp = (float4*)(&s_x[row][0]) + seg * 8;
        #pragma unroll
        for (int q = 0; q < 8; ++q) dp[q] = sp[q];
    }
    __syncthreads();

    float acc[32];
    #pragma unroll
    for (int m = 0; m < 32; ++m) acc[m] = 0.0f;
    const int j = tid;
    const float4* w4p = (const float4*)(Wi + (size_t)j * H);

    #pragma unroll 2
    for (int k4 = 0; k4 < 64; ++k4) {
        float4 wv = w4p[k4];
        #pragma unroll
        for (int m = 0; m < 32; ++m) {
            float4 xv = *(const float4*)&s_x[m][k4 * 4];
            acc[m] = fmaf(wv.x, xv.x, acc[m]);
            acc[m] = fmaf(wv.y, xv.y, acc[m]);
            acc[m] = fmaf(wv.z, xv.z, acc[m]);
            acc[m] = fmaf(wv.w, xv.w, acc[m]);
        }
    }
    float* out = g_P + (size_t)t * (H * B) + (size_t)j * B + bh * 32;
    #pragma unroll
    for (int m4 = 0; m4 < 8; ++m4)
        ((float4*)out)[m4] = make_float4(acc[m4 * 4], acc[m4 * 4 + 1],
                                         acc[m4 * 4 + 2], acc[m4 * 4 + 3]);
}

// ---------------- persistent recurrent kernel: tiled, dataflow sync ---------
// 128 CTAs = 16 j-tiles x 8 b-tiles. CTA owns j in [jt*16, jt*16+16),
// b in [bt*8, bt*8+8). 512 threads: warp = jj (16 warps), lane = nh*8+bb.
// Each thread computes y[j][nh][b] = sum_i Wh[j][nh*256+i] * cand[i][b]
// (256 FFMA) from SMEM-staged cand; tags provide cross-CTA sync.
__global__ __launch_bounds__(512, 1)
void rnn_kernel(const int* __restrict__ input_len,
                const float* __restrict__ bi, const float* __restrict__ bhb,
                const float* __restrict__ Wh) {
    extern __shared__ float sm[];
    float* s_W = sm;                    // [16][4][WROW]  ~66.6 KB
    float* s_c = sm + JC * NH * WROW;   // [2][8][WROW]   ~16.6 KB

    const int tid = threadIdx.x, cid = blockIdx.x;
    const int jt = cid & 15, bt = cid >> 4;
    const int jj = tid >> 5, lane = tid & 31;
    const int nh = lane >> 3, bb = lane & 7;
    const int j = jt * JC + jj;
    const int b = bt * BC + bb;

    // load weights: s_W[(jj*4+nh)*WROW + i] = Wh[(jt*16+jj)*1024 + nh*256 + i]
    {
        const float4* src = (const float4*)(Wh + (size_t)jt * JC * NHH);
        float4* dst = (float4*)s_W;
        #pragma unroll
        for (int u4 = tid; u4 < 4096; u4 += 512) {
            int row = u4 >> 6, col4 = u4 & 63;          // row<64, col4<64
            dst[row * (WROW / 4) + col4] = src[u4];
        }
    }

    const float bsum = bi[j] + bhb[j];
    const int mylen = input_len[b];
    float z = 0.f, h = 0.f;

    // cand(0) = tanh(P[0] + bias), tag = 0
    float myc = tanhf(g_P[(size_t)j * B + b] + bsum);
    if (nh == 0)
        __stcg(&g_cand[0][j * B + b], (unsigned long long)__float_as_uint(myc));

    // staging mapping (independent of compute mapping):
    //   thread stages words (i = si + 64q, b = bt*8+sb), q = 0..3
    const int si = tid >> 3, sb = tid & 7;
    const int sgb = bt * BC + sb;

    #pragma unroll 1
    for (int t = 0; t < S; ++t) {
        const int p = t & 1;
        const unsigned tagw = (unsigned)t;

        // stage this CTA's cand slice [256 i][8 b] into smem (tag-checked)
        {
            const unsigned long long* gc = g_cand[p];
            float* dst = s_c + p * (BC * WROW) + sb * WROW;
            #pragma unroll
            for (int q = 0; q < 4; ++q) {
                const int i = si + q * 64;
                unsigned long long v = __ldcg(gc + i * B + sgb);
                if ((unsigned)(v >> 32) != tagw) {       // rare: not ready
                    const volatile unsigned long long* vp = gc + i * B + sgb;
                    do { v = *vp; } while ((unsigned)(v >> 32) != tagw);
                }
                dst[i] = __uint_as_float((unsigned)v);
            }
        }
        // per-thread prefetches (overlap staging latency)
        float pnext = (t < S - 1)
            ? __ldcg(&g_P[(size_t)(t + 1) * (H * B) + (size_t)j * B + b]) : 0.f;
        float gt = __ldcg(&g_gate[(size_t)t * (B * NH) + b * NH + nh]);
        __syncthreads();

        // y = sum_i w[i] * cand[i][bb]  (64 x float4, conflict-free LDS)
        const float4* wv = (const float4*)(s_W + (jj * NH + nh) * WROW);
        const float4* cv = (const float4*)(s_c + p * (BC * WROW) + bb * WROW);
        float acc0 = 0.f, acc1 = 0.f, acc2 = 0.f, acc3 = 0.f;
        #pragma unroll 16
        for (int m = 0; m < 64; m += 4) {
            float4 c0 = cv[m],     w0 = wv[m];
            float4 c1 = cv[m + 1], w1 = wv[m + 1];
            float4 c2 = cv[m + 2], w2 = wv[m + 2];
            float4 c3 = cv[m + 3], w3 = wv[m + 3];
            acc0 = fmaf(w0.x, c0.x, acc0); acc0 = fmaf(w0.y, c0.y, acc0);
            acc0 = fmaf(w0.z, c0.z, acc0); acc0 = fmaf(w0.w, c0.w, acc0);
            acc1 = fmaf(w1.x, c1.x, acc1); acc1 = fmaf(w1.y, c1.y, acc1);
            acc1 = fmaf(w1.z, c1.z, acc1); acc1 = fmaf(w1.w, c1.w, acc1);
            acc2 = fmaf(w2.x, c2.x, acc2); acc2 = fmaf(w2.y, c2.y, acc2);
            acc2 = fmaf(w2.z, c2.z, acc2); acc2 = fmaf(w2.w, c2.w, acc2);
            acc3 = fmaf(w3.x, c3.x, acc3); acc3 = fmaf(w3.y, c3.y, acc3);
            acc3 = fmaf(w3.z, c3.z, acc3); acc3 = fmaf(w3.w, c3.w, acc3);
        }
        const float y = (acc0 + acc1) + (acc2 + acc3);

        // z' = z + g*(y - z); h' = h + g*(cand - h)
        z = fmaf(gt, y - z, z);
        h = fmaf(gt, myc - h, h);

        if (t == mylen - 1)
            g_sel[b * NHH + nh * H + j] = h;

        // sum z over the 4 nh lanes (lane = nh*8+bb -> xor 8, 16)
        float zs = z;
        zs += __shfl_xor_sync(0xffffffffu, zs, 8);
        zs += __shfl_xor_sync(0xffffffffu, zs, 16);

        if (t < S - 1) {
            myc = tanhf(pnext + bsum + zs);
            if (nh == 0) {
                unsigned long long pk =
                    ((unsigned long long)(unsigned)(t + 1) << 32) |
                    (unsigned long long)__float_as_uint(myc);
                __stcg(&g_cand[(t + 1) & 1][j * B + b], pk);
            }
        }
    }
}

// ---------------- readout ---------------------------------------------------
__global__ __launch_bounds__(256)
void final_fc_kernel(const float* __restrict__ fc1_W,
                     const float* __restrict__ fc1_b,
                     const float* __restrict__ fc2_W,
                     const float* __restrict__ fc2_b,
                     float* __restrict__ out) {
    __shared__ float selsh[NHH];
    __shared__ float red0[H];
    __shared__ float red1[H];
    const int b = blockIdx.x;
    const int j = threadIdx.x;

    #pragma unroll
    for (int i = 0; i < NH; ++i)
        selsh[i * H + j] = g_sel[b * NHH + i * H + j];
    __syncthreads();

    float s = fc1_b[j];
    const float4* w = (const float4*)(fc1_W + (size_t)j * NHH);
    #pragma unroll 4
    for (int k4 = 0; k4 < NHH / 4; ++k4) {
        float4 wv = w[k4];
        float4 sv = *(const float4*)&selsh[k4 * 4];
        s = fmaf(wv.x, sv.x, s);
        s = fmaf(wv.y, sv.y, s);
        s = fmaf(wv.z, sv.z, s);
        s = fmaf(wv.w, sv.w, s);
    }
    s = tanhf(s);
    red0[j] = s * fc2_W[j];
    red1[j] = s * fc2_W[H + j];
    __syncthreads();

    for (int stride = 128; stride >= 1; stride >>= 1) {
        if (j < stride) {
            red0[j] += red0[j + stride];
            red1[j] += red1[j + stride];
        }
        __syncthreads();
    }
    if (j == 0) {
        out[b * 2 + 0] = red0[0] + fc2_b[0];
        out[b * 2 + 1] = red1[0] + fc2_b[1];
    }
}

// ---------------------------------------------------------------------------
extern "C" void kernel_launch(void* const* d_in, const int* in_sizes, int n_in,
                              void* d_out, int out_size) {
    const int*   src       = (const int*)  d_in[0];
    const int*   input_len = (const int*)  d_in[1];
    const float* fix_src   = (const float*)d_in[2];
    const float* emb_table = (const float*)d_in[3];
    const float* Wi        = (const float*)d_in[4];
    const float* bi        = (const float*)d_in[5];
    const float* Wh        = (const float*)d_in[6];
    const float* bh        = (const float*)d_in[7];
    const float* fc1_W     = (const float*)d_in[8];
    const float* fc1_b     = (const float*)d_in[9];
    const float* fc2_W     = (const float*)d_in[10];
    const float* fc2_b     = (const float*)d_in[11];
    float* out = (float*)d_out;

    const int rnn_smem = (JC * NH * WROW + 2 * BC * WROW) * 4;   // 83200 B
    cudaFuncSetAttribute(rnn_kernel,
                         cudaFuncAttributeMaxDynamicSharedMemorySize, rnn_smem);

    init_kernel<<<64, 256>>>();                 // clear cand tags (replay-safe)
    gate_kernel<<<S, 256>>>(fix_src);
    p_kernel<<<2 * S, 256>>>(src, emb_table, Wi);
    rnn_kernel<<<NCTA, 512, rnn_smem>>>(input_len, bi, bh, Wh);
    final_fc_kernel<<<B, 256>>>(fc1_W, fc1_b, fc2_W, fc2_b, out);
}